// round 1
// baseline (speedup 1.0000x reference)
#include <cuda_runtime.h>
#include <cstdint>

#define N_NODES 100000
#define N_EDGES 1250000
#define D 64

// Scratch: h = x + agg, built in place. 100000*64 floats = 25.6 MB.
__device__ __align__(16) float g_h[(size_t)N_NODES * D];
__device__ int g_idx_is64;

// ---------------------------------------------------------------------------
// Kernel 0: detect whether edge_index is int64 or int32.
// If int64 (little-endian) every odd 32-bit word is the high half of a value
// in [0, 100000) => zero. With int32 data those words are random node ids;
// 64 of them all being zero has probability ~1e-320.
// ---------------------------------------------------------------------------
__global__ void detect_idx_dtype(const int* __restrict__ ei32) {
    if (blockIdx.x == 0 && threadIdx.x == 0) {
        int is64 = 1;
        #pragma unroll 1
        for (int i = 1; i < 128; i += 2) {
            if (ei32[i] != 0) { is64 = 0; break; }
        }
        g_idx_is64 = is64;
    }
}

// ---------------------------------------------------------------------------
// Kernel 1: g_h = x  (float4 copy)
// ---------------------------------------------------------------------------
__global__ void init_h(const float4* __restrict__ x4) {
    int i = blockIdx.x * blockDim.x + threadIdx.x;
    if (i < N_NODES * D / 4) {
        reinterpret_cast<float4*>(g_h)[i] = x4[i];
    }
}

// ---------------------------------------------------------------------------
// Kernel 2: scatter-add. 16 threads per edge, one float4 chunk each.
// Vector L2 reduction via red.global.add.v4.f32 (sm_90+).
// ---------------------------------------------------------------------------
__global__ void scatter_edges(const void* __restrict__ ei,
                              const float* __restrict__ x) {
    long long idx = (long long)blockIdx.x * blockDim.x + threadIdx.x;
    if (idx >= (long long)N_EDGES * 16) return;
    int e = (int)(idx >> 4);
    int c = (int)(idx & 15);

    long long s, d;
    if (g_idx_is64) {
        const long long* p = (const long long*)ei;
        s = p[e];
        d = p[N_EDGES + e];
    } else {
        const int* p = (const int*)ei;
        s = p[e];
        d = p[N_EDGES + e];
    }

    float4 v = *reinterpret_cast<const float4*>(x + s * D + c * 4);
    float* dst = g_h + d * D + c * 4;
    asm volatile("red.global.add.v4.f32 [%0], {%1, %2, %3, %4};"
                 :: "l"(dst), "f"(v.x), "f"(v.y), "f"(v.z), "f"(v.w)
                 : "memory");
}

// ---------------------------------------------------------------------------
// Kernel 3: fused MLP. One warp per node. Lane l owns output cols {l, l+32}.
// W1/W2/b1/b2 staged in shared memory; h row broadcast via shuffles.
// ---------------------------------------------------------------------------
__global__ __launch_bounds__(256) void mlp_kernel(
    const float* __restrict__ W1, const float* __restrict__ b1,
    const float* __restrict__ W2, const float* __restrict__ b2,
    float* __restrict__ out)
{
    __shared__ float W1s[D * D];
    __shared__ float W2s[D * D];
    __shared__ float b1s[D];
    __shared__ float b2s[D];

    for (int i = threadIdx.x; i < D * D; i += blockDim.x) {
        W1s[i] = W1[i];
        W2s[i] = W2[i];
    }
    if (threadIdx.x < D) {
        b1s[threadIdx.x] = b1[threadIdx.x];
        b2s[threadIdx.x] = b2[threadIdx.x];
    }
    __syncthreads();

    const int lane   = threadIdx.x & 31;
    const int warp   = (blockIdx.x * blockDim.x + threadIdx.x) >> 5;
    const int nwarps = (gridDim.x * blockDim.x) >> 5;

    for (int node = warp; node < N_NODES; node += nwarps) {
        const float* hr = g_h + (long long)node * D;
        float h_lo = hr[lane];
        float h_hi = hr[lane + 32];

        // Layer 1: t = relu(h @ W1 + b1)
        float a0 = b1s[lane];
        float a1 = b1s[lane + 32];
        #pragma unroll
        for (int k = 0; k < 32; k++) {
            float ha = __shfl_sync(0xffffffffu, h_lo, k);
            float hb = __shfl_sync(0xffffffffu, h_hi, k);
            a0 += ha * W1s[k * D + lane]        + hb * W1s[(k + 32) * D + lane];
            a1 += ha * W1s[k * D + lane + 32]   + hb * W1s[(k + 32) * D + lane + 32];
        }
        float t_lo = fmaxf(a0, 0.0f);
        float t_hi = fmaxf(a1, 0.0f);

        // Layer 2: out = t @ W2 + b2
        float o0 = b2s[lane];
        float o1 = b2s[lane + 32];
        #pragma unroll
        for (int k = 0; k < 32; k++) {
            float ta = __shfl_sync(0xffffffffu, t_lo, k);
            float tb = __shfl_sync(0xffffffffu, t_hi, k);
            o0 += ta * W2s[k * D + lane]        + tb * W2s[(k + 32) * D + lane];
            o1 += ta * W2s[k * D + lane + 32]   + tb * W2s[(k + 32) * D + lane + 32];
        }

        float* orow = out + (long long)node * D;
        orow[lane]      = o0;
        orow[lane + 32] = o1;
    }
}

// ---------------------------------------------------------------------------
// Launch
// Inputs (metadata order): x, edge_index, W1, b1, W2, b2
// ---------------------------------------------------------------------------
extern "C" void kernel_launch(void* const* d_in, const int* in_sizes, int n_in,
                              void* d_out, int out_size) {
    const float* x  = (const float*)d_in[0];
    const void*  ei = d_in[1];
    const float* W1 = (const float*)d_in[2];
    const float* b1 = (const float*)d_in[3];
    const float* W2 = (const float*)d_in[4];
    const float* b2 = (const float*)d_in[5];
    float* out = (float*)d_out;

    detect_idx_dtype<<<1, 32>>>((const int*)ei);

    {
        int n4 = N_NODES * D / 4;
        init_h<<<(n4 + 255) / 256, 256>>>((const float4*)x);
    }

    {
        long long total = (long long)N_EDGES * 16;
        int blocks = (int)((total + 255) / 256);
        scatter_edges<<<blocks, 256>>>(ei, x);
    }

    {
        // one warp per node: 100000 warps = 12500 blocks of 256 threads
        mlp_kernel<<<12500, 256>>>(W1, b1, W2, b2, out);
    }
}

// round 2
// speedup vs baseline: 1.9747x; 1.9747x over previous
#include <cuda_runtime.h>
#include <cstdint>

#define N_NODES 100000
#define N_EDGES 1250000
#define D 64

// Scratch: aggregation buffer (scatter-add target). 25.6 MB.
__device__ __align__(16) float g_agg[(size_t)N_NODES * D];
__device__ int g_idx_is64;

// ---------------------------------------------------------------------------
// Kernel 0: detect whether edge_index is int64 or int32.
// If int64 (little-endian) every odd 32-bit word is the high half of a value
// in [0, 100000) => zero. With int32 data those words are random node ids.
// ---------------------------------------------------------------------------
__global__ void detect_idx_dtype(const int* __restrict__ ei32) {
    if (blockIdx.x == 0 && threadIdx.x == 0) {
        int is64 = 1;
        #pragma unroll 1
        for (int i = 1; i < 128; i += 2) {
            if (ei32[i] != 0) { is64 = 0; break; }
        }
        g_idx_is64 = is64;
    }
}

// ---------------------------------------------------------------------------
// Kernel 1: zero the aggregation buffer (float4 stores).
// ---------------------------------------------------------------------------
__global__ void zero_agg() {
    int i = blockIdx.x * blockDim.x + threadIdx.x;
    if (i < N_NODES * D / 4) {
        reinterpret_cast<float4*>(g_agg)[i] = make_float4(0.f, 0.f, 0.f, 0.f);
    }
}

// ---------------------------------------------------------------------------
// Kernel 2: scatter-add. 16 threads per edge, one float4 chunk each.
// Vector L2 reduction via red.global.add.v4.f32 (sm_90+).
// ---------------------------------------------------------------------------
__global__ void scatter_edges(const void* __restrict__ ei,
                              const float* __restrict__ x) {
    long long idx = (long long)blockIdx.x * blockDim.x + threadIdx.x;
    if (idx >= (long long)N_EDGES * 16) return;
    int e = (int)(idx >> 4);
    int c = (int)(idx & 15);

    long long s, d;
    if (g_idx_is64) {
        const long long* p = (const long long*)ei;
        s = p[e];
        d = p[N_EDGES + e];
    } else {
        const int* p = (const int*)ei;
        s = p[e];
        d = p[N_EDGES + e];
    }

    float4 v = *reinterpret_cast<const float4*>(x + s * D + c * 4);
    float* dst = g_agg + d * D + c * 4;
    asm volatile("red.global.add.v4.f32 [%0], {%1, %2, %3, %4};"
                 :: "l"(dst), "f"(v.x), "f"(v.y), "f"(v.z), "f"(v.w)
                 : "memory");
}

// ---------------------------------------------------------------------------
// Kernel 3: fused MLP, register-tiled.
// Block = 256 threads as (tx 0..15, ty 0..15). Tile = 64 nodes x 64 cols.
// Thread (tx,ty) computes nodes ty*4..+3, cols tx*4..+3 (4x4 register tile).
// h tile (x + agg) lives in smem node-major; ReLU output overwrites it.
// ---------------------------------------------------------------------------
#define HS_STRIDE 68  // 64 + 4 pad, keeps 16B alignment, avoids bank conflicts

__global__ __launch_bounds__(256) void mlp_kernel(
    const float* __restrict__ x,
    const float* __restrict__ W1, const float* __restrict__ b1,
    const float* __restrict__ W2, const float* __restrict__ b2,
    float* __restrict__ out)
{
    __shared__ float W1s[D * D];
    __shared__ float W2s[D * D];
    __shared__ float hs[64][HS_STRIDE];

    const int tid = threadIdx.x;
    const int tx = tid & 15;
    const int ty = tid >> 4;
    const int node_base = blockIdx.x * 64;

    // Stage weights (k-major: W[k][col], exactly the input layout).
    #pragma unroll
    for (int i = tid; i < D * D; i += 256) {
        W1s[i] = W1[i];
        W2s[i] = W2[i];
    }

    // Stage h tile: 64 nodes x 64 floats = 1024 float4, 4 per thread.
    #pragma unroll
    for (int j = 0; j < 4; j++) {
        int f = tid + j * 256;          // float4 index within tile
        int nd = f >> 4;                // node within tile (0..63)
        int kc = f & 15;                // float4 chunk within row (0..15)
        int g = node_base + nd;
        float4 v = make_float4(0.f, 0.f, 0.f, 0.f);
        if (g < N_NODES) {
            float4 xv = reinterpret_cast<const float4*>(x)[(size_t)g * 16 + kc];
            float4 av = reinterpret_cast<const float4*>(g_agg)[(size_t)g * 16 + kc];
            v = make_float4(xv.x + av.x, xv.y + av.y, xv.z + av.z, xv.w + av.w);
        }
        *reinterpret_cast<float4*>(&hs[nd][kc * 4]) = v;
    }
    __syncthreads();

    // ---- Layer 1: t = relu(h @ W1 + b1) ----
    float acc[4][4];
    {
        float4 bv = reinterpret_cast<const float4*>(b1)[tx];
        #pragma unroll
        for (int r = 0; r < 4; r++) {
            acc[r][0] = bv.x; acc[r][1] = bv.y; acc[r][2] = bv.z; acc[r][3] = bv.w;
        }
    }
    #pragma unroll 8
    for (int k = 0; k < D; k++) {
        float4 w = *reinterpret_cast<const float4*>(&W1s[k * D + tx * 4]);
        float h0 = hs[ty * 4 + 0][k];
        float h1 = hs[ty * 4 + 1][k];
        float h2 = hs[ty * 4 + 2][k];
        float h3 = hs[ty * 4 + 3][k];
        acc[0][0] += h0 * w.x; acc[0][1] += h0 * w.y; acc[0][2] += h0 * w.z; acc[0][3] += h0 * w.w;
        acc[1][0] += h1 * w.x; acc[1][1] += h1 * w.y; acc[1][2] += h1 * w.z; acc[1][3] += h1 * w.w;
        acc[2][0] += h2 * w.x; acc[2][1] += h2 * w.y; acc[2][2] += h2 * w.z; acc[2][3] += h2 * w.w;
        acc[3][0] += h3 * w.x; acc[3][1] += h3 * w.y; acc[3][2] += h3 * w.z; acc[3][3] += h3 * w.w;
    }
    __syncthreads();  // all reads of hs done

    // ReLU and write t back into hs (node-major, STS.128 conflict-free).
    #pragma unroll
    for (int r = 0; r < 4; r++) {
        float4 t;
        t.x = fmaxf(acc[r][0], 0.f);
        t.y = fmaxf(acc[r][1], 0.f);
        t.z = fmaxf(acc[r][2], 0.f);
        t.w = fmaxf(acc[r][3], 0.f);
        *reinterpret_cast<float4*>(&hs[ty * 4 + r][tx * 4]) = t;
    }
    __syncthreads();

    // ---- Layer 2: out = t @ W2 + b2 ----
    {
        float4 bv = reinterpret_cast<const float4*>(b2)[tx];
        #pragma unroll
        for (int r = 0; r < 4; r++) {
            acc[r][0] = bv.x; acc[r][1] = bv.y; acc[r][2] = bv.z; acc[r][3] = bv.w;
        }
    }
    #pragma unroll 8
    for (int k = 0; k < D; k++) {
        float4 w = *reinterpret_cast<const float4*>(&W2s[k * D + tx * 4]);
        float h0 = hs[ty * 4 + 0][k];
        float h1 = hs[ty * 4 + 1][k];
        float h2 = hs[ty * 4 + 2][k];
        float h3 = hs[ty * 4 + 3][k];
        acc[0][0] += h0 * w.x; acc[0][1] += h0 * w.y; acc[0][2] += h0 * w.z; acc[0][3] += h0 * w.w;
        acc[1][0] += h1 * w.x; acc[1][1] += h1 * w.y; acc[1][2] += h1 * w.z; acc[1][3] += h1 * w.w;
        acc[2][0] += h2 * w.x; acc[2][1] += h2 * w.y; acc[2][2] += h2 * w.z; acc[2][3] += h2 * w.w;
        acc[3][0] += h3 * w.x; acc[3][1] += h3 * w.y; acc[3][2] += h3 * w.z; acc[3][3] += h3 * w.w;
    }

    // Store output (coalesced float4).
    #pragma unroll
    for (int r = 0; r < 4; r++) {
        int g = node_base + ty * 4 + r;
        if (g < N_NODES) {
            float4 o = make_float4(acc[r][0], acc[r][1], acc[r][2], acc[r][3]);
            reinterpret_cast<float4*>(out)[(size_t)g * 16 + tx] = o;
        }
    }
}

// ---------------------------------------------------------------------------
// Launch
// Inputs (metadata order): x, edge_index, W1, b1, W2, b2
// ---------------------------------------------------------------------------
extern "C" void kernel_launch(void* const* d_in, const int* in_sizes, int n_in,
                              void* d_out, int out_size) {
    const float* x  = (const float*)d_in[0];
    const void*  ei = d_in[1];
    const float* W1 = (const float*)d_in[2];
    const float* b1 = (const float*)d_in[3];
    const float* W2 = (const float*)d_in[4];
    const float* b2 = (const float*)d_in[5];
    float* out = (float*)d_out;

    detect_idx_dtype<<<1, 32>>>((const int*)ei);

    {
        int n4 = N_NODES * D / 4;
        zero_agg<<<(n4 + 255) / 256, 256>>>();
    }

    {
        long long total = (long long)N_EDGES * 16;
        int blocks = (int)((total + 255) / 256);
        scatter_edges<<<blocks, 256>>>(ei, x);
    }

    {
        int blocks = (N_NODES + 63) / 64;  // 1563
        mlp_kernel<<<blocks, 256>>>(x, W1, b1, W2, b2, out);
    }
}

// round 3
// speedup vs baseline: 2.1619x; 1.0948x over previous
#include <cuda_runtime.h>
#include <cstdint>

#define N_NODES 100000
#define N_EDGES 1250000
#define D 64
#define NB 196  // ceil(N_NODES / 512) scan blocks

// ---- device scratch (no allocation allowed) ----
__device__ __align__(16) float g_h[(size_t)N_NODES * D];  // h = x + agg
__device__ int g_cnt[N_NODES];       // histogram, then fill cursor
__device__ int g_off[N_NODES + 1];   // CSR offsets
__device__ int g_csr[N_EDGES];       // src node per CSR slot
__device__ int g_bsum[NB];           // scan block sums
__device__ int g_idx_is64;

// ---------------------------------------------------------------------------
// Kernel: zero counters, set g_off[N], detect edge_index dtype.
// int64 little-endian => every odd 32-bit word of values < 100000 is zero.
// ---------------------------------------------------------------------------
__global__ void init_kernel(const int* __restrict__ ei32) {
    int i = blockIdx.x * blockDim.x + threadIdx.x;
    if (i < N_NODES) g_cnt[i] = 0;
    if (blockIdx.x == 0 && threadIdx.x == 0) {
        g_off[N_NODES] = N_EDGES;
        int is64 = 1;
        #pragma unroll 1
        for (int k = 1; k < 128; k += 2) {
            if (ei32[k] != 0) { is64 = 0; break; }
        }
        g_idx_is64 = is64;
    }
}

// ---------------------------------------------------------------------------
// Kernel: histogram of dst.
// ---------------------------------------------------------------------------
__global__ void hist_kernel(const void* __restrict__ ei) {
    int e = blockIdx.x * blockDim.x + threadIdx.x;
    if (e >= N_EDGES) return;
    int d;
    if (g_idx_is64) d = (int)((const long long*)ei)[N_EDGES + e];
    else            d = ((const int*)ei)[N_EDGES + e];
    atomicAdd(&g_cnt[d], 1);
}

// ---------------------------------------------------------------------------
// Scan kernels: exclusive prefix sum of g_cnt -> g_off (and cursor copy).
// ---------------------------------------------------------------------------
__global__ __launch_bounds__(512) void scanA_kernel() {
    __shared__ int sm[512];
    int t = threadIdx.x;
    int i = blockIdx.x * 512 + t;
    sm[t] = (i < N_NODES) ? g_cnt[i] : 0;
    __syncthreads();
    #pragma unroll
    for (int s = 256; s > 0; s >>= 1) {
        if (t < s) sm[t] += sm[t + s];
        __syncthreads();
    }
    if (t == 0) g_bsum[blockIdx.x] = sm[0];
}

__global__ __launch_bounds__(256) void scanB_kernel() {
    __shared__ int sm[256];
    int t = threadIdx.x;
    int v = (t < NB) ? g_bsum[t] : 0;
    sm[t] = v;
    __syncthreads();
    #pragma unroll
    for (int s = 1; s < 256; s <<= 1) {
        int a = (t >= s) ? sm[t - s] : 0;
        __syncthreads();
        sm[t] += a;
        __syncthreads();
    }
    if (t < NB) g_bsum[t] = sm[t] - v;  // exclusive
}

__global__ __launch_bounds__(512) void scanC_kernel() {
    __shared__ int sm[512];
    int t = threadIdx.x;
    int i = blockIdx.x * 512 + t;
    int v = (i < N_NODES) ? g_cnt[i] : 0;
    sm[t] = v;
    __syncthreads();
    #pragma unroll
    for (int s = 1; s < 512; s <<= 1) {
        int a = (t >= s) ? sm[t - s] : 0;
        __syncthreads();
        sm[t] += a;
        __syncthreads();
    }
    if (i < N_NODES) {
        int excl = sm[t] - v + g_bsum[blockIdx.x];
        g_off[i] = excl;
        g_cnt[i] = excl;  // cursor for fill
    }
}

// ---------------------------------------------------------------------------
// Kernel: fill CSR slots. pos = cursor[dst]++, csr[pos] = src.
// ---------------------------------------------------------------------------
__global__ void fill_kernel(const void* __restrict__ ei) {
    int e = blockIdx.x * blockDim.x + threadIdx.x;
    if (e >= N_EDGES) return;
    int s, d;
    if (g_idx_is64) {
        const long long* p = (const long long*)ei;
        s = (int)p[e];
        d = (int)p[N_EDGES + e];
    } else {
        const int* p = (const int*)ei;
        s = p[e];
        d = p[N_EDGES + e];
    }
    int pos = atomicAdd(&g_cnt[d], 1);
    g_csr[pos] = s;
}

// ---------------------------------------------------------------------------
// Kernel: gather-sum. One warp per node: h[n] = x[n] + sum_{src} x[src].
// ---------------------------------------------------------------------------
__global__ __launch_bounds__(256) void gather_kernel(const float* __restrict__ x) {
    int gw = (blockIdx.x * blockDim.x + threadIdx.x) >> 5;
    int lane = threadIdx.x & 31;
    if (gw >= N_NODES) return;

    int beg = g_off[gw];
    int end = g_off[gw + 1];

    float a0 = x[(size_t)gw * D + lane];
    float a1 = x[(size_t)gw * D + lane + 32];

    int j = beg;
    // unroll by 2 for a bit of MLP
    for (; j + 1 < end; j += 2) {
        int s0 = g_csr[j];
        int s1 = g_csr[j + 1];
        float v00 = x[(size_t)s0 * D + lane];
        float v01 = x[(size_t)s0 * D + lane + 32];
        float v10 = x[(size_t)s1 * D + lane];
        float v11 = x[(size_t)s1 * D + lane + 32];
        a0 += v00; a1 += v01;
        a0 += v10; a1 += v11;
    }
    if (j < end) {
        int s0 = g_csr[j];
        a0 += x[(size_t)s0 * D + lane];
        a1 += x[(size_t)s0 * D + lane + 32];
    }

    g_h[(size_t)gw * D + lane]      = a0;
    g_h[(size_t)gw * D + lane + 32] = a1;
}

// ---------------------------------------------------------------------------
// Kernel: fused MLP, register-tiled, k-blocked by 4.
// Block = 256 threads (tx 0..15, ty 0..15); tile = 64 nodes x 64 cols.
// Thread (tx,ty): nodes ty*4..+3, cols tx*4..+3.
// ---------------------------------------------------------------------------
#define HS_STRIDE 68  // 64 + 4 pad; multiple of 4 keeps float4 alignment

__global__ __launch_bounds__(256) void mlp_kernel(
    const float* __restrict__ W1, const float* __restrict__ b1,
    const float* __restrict__ W2, const float* __restrict__ b2,
    float* __restrict__ out)
{
    __shared__ float W1s[D * D];
    __shared__ float W2s[D * D];
    __shared__ float hs[64][HS_STRIDE];

    const int tid = threadIdx.x;
    const int tx = tid & 15;
    const int ty = tid >> 4;
    const int node_base = blockIdx.x * 64;

    #pragma unroll
    for (int i = tid; i < D * D; i += 256) {
        W1s[i] = W1[i];
        W2s[i] = W2[i];
    }

    // Stage h tile: 64 nodes x 16 float4, 4 per thread.
    #pragma unroll
    for (int j = 0; j < 4; j++) {
        int f = tid + j * 256;
        int nd = f >> 4;
        int kc = f & 15;
        int g = node_base + nd;
        float4 v = make_float4(0.f, 0.f, 0.f, 0.f);
        if (g < N_NODES) {
            v = reinterpret_cast<const float4*>(g_h)[(size_t)g * 16 + kc];
        }
        *reinterpret_cast<float4*>(&hs[nd][kc * 4]) = v;
    }
    __syncthreads();

    float acc[4][4];

    // ---- Layer 1: t = relu(h @ W1 + b1) ----
    {
        float4 bv = reinterpret_cast<const float4*>(b1)[tx];
        #pragma unroll
        for (int r = 0; r < 4; r++) {
            acc[r][0] = bv.x; acc[r][1] = bv.y; acc[r][2] = bv.z; acc[r][3] = bv.w;
        }
    }
    #pragma unroll 4
    for (int k0 = 0; k0 < D; k0 += 4) {
        float hr[4][4];
        #pragma unroll
        for (int r = 0; r < 4; r++) {
            *reinterpret_cast<float4*>(hr[r]) =
                *reinterpret_cast<const float4*>(&hs[ty * 4 + r][k0]);
        }
        #pragma unroll
        for (int kk = 0; kk < 4; kk++) {
            float4 w = *reinterpret_cast<const float4*>(&W1s[(k0 + kk) * D + tx * 4]);
            #pragma unroll
            for (int r = 0; r < 4; r++) {
                acc[r][0] += hr[r][kk] * w.x;
                acc[r][1] += hr[r][kk] * w.y;
                acc[r][2] += hr[r][kk] * w.z;
                acc[r][3] += hr[r][kk] * w.w;
            }
        }
    }
    __syncthreads();

    // ReLU, write t back into hs (node-major STS.128).
    #pragma unroll
    for (int r = 0; r < 4; r++) {
        float4 t;
        t.x = fmaxf(acc[r][0], 0.f);
        t.y = fmaxf(acc[r][1], 0.f);
        t.z = fmaxf(acc[r][2], 0.f);
        t.w = fmaxf(acc[r][3], 0.f);
        *reinterpret_cast<float4*>(&hs[ty * 4 + r][tx * 4]) = t;
    }
    __syncthreads();

    // ---- Layer 2: out = t @ W2 + b2 ----
    {
        float4 bv = reinterpret_cast<const float4*>(b2)[tx];
        #pragma unroll
        for (int r = 0; r < 4; r++) {
            acc[r][0] = bv.x; acc[r][1] = bv.y; acc[r][2] = bv.z; acc[r][3] = bv.w;
        }
    }
    #pragma unroll 4
    for (int k0 = 0; k0 < D; k0 += 4) {
        float hr[4][4];
        #pragma unroll
        for (int r = 0; r < 4; r++) {
            *reinterpret_cast<float4*>(hr[r]) =
                *reinterpret_cast<const float4*>(&hs[ty * 4 + r][k0]);
        }
        #pragma unroll
        for (int kk = 0; kk < 4; kk++) {
            float4 w = *reinterpret_cast<const float4*>(&W2s[(k0 + kk) * D + tx * 4]);
            #pragma unroll
            for (int r = 0; r < 4; r++) {
                acc[r][0] += hr[r][kk] * w.x;
                acc[r][1] += hr[r][kk] * w.y;
                acc[r][2] += hr[r][kk] * w.z;
                acc[r][3] += hr[r][kk] * w.w;
            }
        }
    }

    #pragma unroll
    for (int r = 0; r < 4; r++) {
        int g = node_base + ty * 4 + r;
        if (g < N_NODES) {
            float4 o = make_float4(acc[r][0], acc[r][1], acc[r][2], acc[r][3]);
            reinterpret_cast<float4*>(out)[(size_t)g * 16 + tx] = o;
        }
    }
}

// ---------------------------------------------------------------------------
// Launch. Inputs (metadata order): x, edge_index, W1, b1, W2, b2
// ---------------------------------------------------------------------------
extern "C" void kernel_launch(void* const* d_in, const int* in_sizes, int n_in,
                              void* d_out, int out_size) {
    const float* x  = (const float*)d_in[0];
    const void*  ei = d_in[1];
    const float* W1 = (const float*)d_in[2];
    const float* b1 = (const float*)d_in[3];
    const float* W2 = (const float*)d_in[4];
    const float* b2 = (const float*)d_in[5];
    float* out = (float*)d_out;

    init_kernel<<<(N_NODES + 255) / 256, 256>>>((const int*)ei);

    int eblocks = (N_EDGES + 255) / 256;
    hist_kernel<<<eblocks, 256>>>(ei);

    scanA_kernel<<<NB, 512>>>();
    scanB_kernel<<<1, 256>>>();
    scanC_kernel<<<NB, 512>>>();

    fill_kernel<<<eblocks, 256>>>(ei);

    gather_kernel<<<(N_NODES * 32 + 255) / 256, 256>>>(x);

    mlp_kernel<<<(N_NODES + 63) / 64, 256>>>(W1, b1, W2, b2, out);
}